// round 15
// baseline (speedup 1.0000x reference)
#include <cuda_runtime.h>
#include <cuda_fp16.h>
#include <math.h>

#define BATCH 4096
#define DIM 1024
#define NG 1024
#define NSPLIT 32            // column splits (one per by-CTA after wn merge)
#define TEMP_INV 10.0f

// ---------------- scratch ----------------------------------------------------
__device__ __align__(16) unsigned short g_qh[BATCH * DIM];
__device__ __align__(16) unsigned short g_ah[BATCH * DIM];

__device__ float  g_w[BATCH];
__device__ __align__(16) float g_part[BATCH * NSPLIT * 8];  // packed: m,s,mv,mj,dot,wr,pad,pad
__device__ double g_loss;
__device__ int    g_acc;
__device__ unsigned g_ticket;

// ---------------- PTX helpers -------------------------------------------------
__device__ __forceinline__ unsigned smem_u32(const void* p) {
    unsigned a;
    asm("{ .reg .u64 t; cvta.to.shared.u64 t, %1; cvt.u32.u64 %0, t; }" : "=r"(a) : "l"(p));
    return a;
}

__device__ __forceinline__ void cp16(unsigned dst, const void* src) {
    asm volatile("cp.async.cg.shared.global [%0], [%1], 16;" :: "r"(dst), "l"(src) : "memory");
}
__device__ __forceinline__ void cp_commit() {
    asm volatile("cp.async.commit_group;" ::: "memory");
}
template <int N>
__device__ __forceinline__ void cp_wait() {
    asm volatile("cp.async.wait_group %0;" :: "n"(N) : "memory");
}

__device__ __forceinline__ void ldsm4(unsigned& r0, unsigned& r1, unsigned& r2, unsigned& r3,
                                      unsigned addr) {
    asm volatile("ldmatrix.sync.aligned.m8n8.x4.shared.b16 {%0,%1,%2,%3}, [%4];"
        : "=r"(r0), "=r"(r1), "=r"(r2), "=r"(r3) : "r"(addr));
}

__device__ __forceinline__ void mma_f16(float* c, unsigned a0, unsigned a1, unsigned a2,
                                        unsigned a3, unsigned b0, unsigned b1) {
    asm volatile(
        "mma.sync.aligned.m16n8k16.row.col.f32.f16.f16.f32 "
        "{%0,%1,%2,%3}, {%4,%5,%6,%7}, {%8,%9}, {%0,%1,%2,%3};"
        : "+f"(c[0]), "+f"(c[1]), "+f"(c[2]), "+f"(c[3])
        : "r"(a0), "r"(a1), "r"(a2), "r"(a3), "r"(b0), "r"(b1));
}

// ---------------- fused convert + weight prep ---------------------------------
// Blocks 0..4095: fp32->fp16 convert (2048 per matrix). Block 4096: weight prep.
__global__ void __launch_bounds__(256) k_pre(const float* __restrict__ scores,
                                             const float* __restrict__ ranks,
                                             const int* __restrict__ qid,
                                             const float* __restrict__ Q,
                                             const float* __restrict__ A) {
    __shared__ int   smax[NG];
    __shared__ int   smin[NG];
    __shared__ float wsum[NG];
    const int tid = threadIdx.x;
    const int b = blockIdx.x;

    if (b < 4096) {
        const int mtx = b >> 11;                    // 0: Q, 1: A
        const int idx = (b & 2047) * 256 + tid;     // 0 .. 524287
        const float* src = (mtx == 0) ? Q : A;
        unsigned short* dh = (mtx == 0) ? g_qh : g_ah;

        size_t e0 = (size_t)idx * 8;
        float4 f0 = *(const float4*)(src + e0);
        float4 f1 = *(const float4*)(src + e0 + 4);
        float v[8] = {f0.x, f0.y, f0.z, f0.w, f1.x, f1.y, f1.z, f1.w};

        unsigned short hs[8];
#pragma unroll
        for (int i = 0; i < 8; i++) hs[i] = __half_as_ushort(__float2half_rn(v[i]));
        uint4 hp;
        hp.x = (unsigned)hs[0] | ((unsigned)hs[1] << 16);
        hp.y = (unsigned)hs[2] | ((unsigned)hs[3] << 16);
        hp.z = (unsigned)hs[4] | ((unsigned)hs[5] << 16);
        hp.w = (unsigned)hs[6] | ((unsigned)hs[7] << 16);
        *(uint4*)(dh + e0) = hp;
        return;
    }

    // ---- weight prep (single CTA) ----
    for (int i = tid; i < NG; i += 256) {
        smax[i] = 0xFF800000;   // -inf bits (scores >= 0 so int order works)
        smin[i] = 0x7F800000;
        wsum[i] = 0.0f;
    }
    if (tid == 0) { g_loss = 0.0; g_acc = 0; g_ticket = 0; }
    __syncthreads();

    for (int i = tid; i < BATCH; i += 256) {
        int g = qid[i];
        int sbits = __float_as_int(scores[i]);
        atomicMax(&smax[g], sbits);
        atomicMin(&smin[g], sbits);
    }
    __syncthreads();

    for (int i = tid; i < BATCH; i += 256) {
        int g = qid[i];
        float w = expf(-0.1f * ranks[i]);
        float mx = __int_as_float(smax[g]);
        float mn = __int_as_float(smin[g]);
        float den = mx - mn;
        float norm = (den > 0.0f) ? (scores[i] - mn) / den : 0.0f;
        w *= expf(0.01f * norm);
        g_w[i] = w;
        atomicAdd(&wsum[g], w);
    }
    __syncthreads();

    for (int i = tid; i < BATCH; i += 256) {
        g_w[i] = g_w[i] / wsum[qid[i]];
    }
}

// ---------------- main: fp16 mma.sync GEMM + fused epilogue -------------------
// Grid (32, 32): CTA tile rows [bx*128,+128) x cols [by*128,+128).
// 8 warps as 4(m) x 2(n); warp tile 32 x 64. BK = 64, 16 k-iters,
// 3-stage cp.async pipeline (one sync per iter).
// smem: sq[128] int @0, sw[128] float @512, stages @1024: 3 x (2 tiles x 18432B)
// After mainloop the stage area is reused as the wn0<-wn1 exchange buffer.
#define TILE_B  18432u            // 128 rows x 72 halfs x 2B (144B stride: LDSM conflict-free)
#define STG_OFF 1024u
#define STG_SZ  (2u * TILE_B)     // 36864
#define NSTAGE  3
#define NKIT    16
#define SMEM_TOTAL (1024 + NSTAGE * 36864)

__global__ void __launch_bounds__(256) k_mma(const int* __restrict__ qid) {
    extern __shared__ char smem[];
    const unsigned sb = smem_u32(smem);
    const int tid = threadIdx.x;
    const int wid = tid >> 5;
    const int lid = tid & 31;
    const int wm = wid & 3;        // m warp 0..3
    const int wn = wid >> 2;       // n warp 0..1
    const int bx = blockIdx.x, by = blockIdx.y;

    // column tables
    if (tid < 128) {
        int c = by * 128 + tid;
        ((int*)(smem))[tid] = qid[c];
        ((float*)(smem + 512))[tid] = g_w[c];
    }

    float acc[2][8][4];
#pragma unroll
    for (int i = 0; i < 2; i++)
#pragma unroll
        for (int j = 0; j < 8; j++)
#pragma unroll
            for (int k = 0; k < 4; k++) acc[i][j][k] = 0.0f;

    // ---- async load of one BK=64 chunk (2 tiles x 128 rows x 128B) ----------
    auto load_chunk = [&](int kc) {
        if (kc < NKIT) {
            unsigned stg = sb + STG_OFF + (unsigned)(kc % NSTAGE) * STG_SZ;
#pragma unroll
            for (int c8 = 0; c8 < 8; c8++) {
                int c = tid + c8 * 256;          // 0..2047
                int tile = c >> 10;              // 0: qh, 1: ah
                int ci = c & 1023;
                int row = ci >> 3;
                int j = ci & 7;
                const unsigned short* base = (tile == 0) ? g_qh : g_ah;
                int grow = ((tile == 0) ? bx : by) * 128 + row;
                const unsigned short* src = base + (size_t)grow * DIM + kc * 64 + 8 * j;
                unsigned dst = stg + tile * TILE_B + row * 144 + 16 * j;
                cp16(dst, src);
            }
        }
        cp_commit();   // constant group count, even past the end
    };

    // A-fragment lane address pieces (row-major m16 x k16 via x4)
    const int a_r = (lid & 15);
    const int a_k = (lid >> 4) << 3;
    // B-fragment lane address pieces (two n8 tiles per x4)
    const int b_n = ((lid >> 4) << 3) + (lid & 7);
    const int b_k = ((lid >> 3) & 1) << 3;

    load_chunk(0);
    load_chunk(1);

    for (int kc = 0; kc < NKIT; kc++) {
        cp_wait<1>();         // chunk kc's own stores complete (kc+1 may pend)
        __syncthreads();      // visibility of chunk kc; frees buf (kc+2)%3
        load_chunk(kc + 2);   // prefetch 2 ahead (empty commit past end)

        unsigned stg = sb + STG_OFF + (unsigned)(kc % NSTAGE) * STG_SZ;
        unsigned qhb = stg;
        unsigned ahb = stg + TILE_B;

#pragma unroll
        for (int ks = 0; ks < 4; ks++) {
            const int ko = ks * 16;
            unsigned a[2][4], b[4][4];
#pragma unroll
            for (int mt = 0; mt < 2; mt++) {
                unsigned ad = qhb + (wm * 32 + mt * 16 + a_r) * 144 + (ko + a_k) * 2;
                ldsm4(a[mt][0], a[mt][1], a[mt][2], a[mt][3], ad);
            }
#pragma unroll
            for (int p = 0; p < 4; p++) {
                unsigned ad = ahb + (wn * 64 + p * 16 + b_n) * 144 + (ko + b_k) * 2;
                ldsm4(b[p][0], b[p][1], b[p][2], b[p][3], ad);
            }
#pragma unroll
            for (int mt = 0; mt < 2; mt++)
#pragma unroll
                for (int p = 0; p < 4; p++) {
                    mma_f16(acc[mt][2 * p],     a[mt][0], a[mt][1], a[mt][2], a[mt][3], b[p][0], b[p][1]);
                    mma_f16(acc[mt][2 * p + 1], a[mt][0], a[mt][1], a[mt][2], a[mt][3], b[p][2], b[p][3]);
                }
        }
    }

    // ---- fused epilogue -----------------------------------------------------
    const int* sq = (const int*)(smem);
    const float* swt = (const float*)(smem + 512);
    const unsigned fullm = 0xffffffffu;

    float rm[4], rs[4], rmv[4], rdot[4], rwr[4];
    int rmj[4];

#pragma unroll
    for (int c4 = 0; c4 < 4; c4++) {
        const int mt = c4 >> 1, h = c4 & 1;
        int row = bx * 128 + wm * 32 + mt * 16 + h * 8 + (lid >> 2);
        int rq = qid[row];
        float m = -1e30f, s = 0.0f, mv = -1e30f, dot = 0.0f, wr = 0.0f;
        int mj = 0;
#pragma unroll
        for (int nt = 0; nt < 8; nt++) {
#pragma unroll
            for (int b = 0; b < 2; b++) {
                float val = acc[mt][nt][2 * h + b] * TEMP_INV;
                int cl = wn * 64 + nt * 8 + 2 * (lid & 3) + b;
                if (val > m) {
                    s = s * __expf(m - val) + 1.0f;
                    m = val;
                } else {
                    s += __expf(val - m);
                }
                if (val > mv) { mv = val; mj = by * 128 + cl; }
                if (sq[cl] == rq) {
                    float wj = swt[cl];
                    dot = fmaf(wj, val, dot);
                    wr += wj;
                }
            }
        }
        // reduce across the 4 lanes owning this row (lanes 4k..4k+3)
#pragma unroll
        for (int off = 2; off > 0; off >>= 1) {
            float om  = __shfl_down_sync(fullm, m, off, 4);
            float os  = __shfl_down_sync(fullm, s, off, 4);
            float omv = __shfl_down_sync(fullm, mv, off, 4);
            int   oj  = __shfl_down_sync(fullm, mj, off, 4);
            float od  = __shfl_down_sync(fullm, dot, off, 4);
            float ow  = __shfl_down_sync(fullm, wr, off, 4);
            float M = fmaxf(m, om);
            s = s * __expf(m - M) + os * __expf(om - M);
            m = M;
            if (omv > mv || (omv == mv && oj < mj)) { mv = omv; mj = oj; }
            dot += od;
            wr += ow;
        }
        rm[c4] = m; rs[c4] = s; rmv[c4] = mv; rmj[c4] = mj; rdot[c4] = dot; rwr[c4] = wr;
    }

    // ---- wn1 -> wn0 exchange through smem, then one packed store per row ----
    cp_wait<0>();          // drain trailing empty groups before reusing stage smem
    __syncthreads();
    float* xch = (float*)(smem + STG_OFF);   // 128 rows x 6 floats

    if (wn == 1 && (lid & 3) == 0) {
#pragma unroll
        for (int c4 = 0; c4 < 4; c4++) {
            int rl = wm * 32 + (c4 >> 1) * 16 + (c4 & 1) * 8 + (lid >> 2);
            float* p = xch + rl * 6;
            p[0] = rm[c4]; p[1] = rs[c4]; p[2] = rmv[c4];
            p[3] = __int_as_float(rmj[c4]); p[4] = rdot[c4]; p[5] = rwr[c4];
        }
    }
    __syncthreads();
    if (wn == 0 && (lid & 3) == 0) {
#pragma unroll
        for (int c4 = 0; c4 < 4; c4++) {
            int rl = wm * 32 + (c4 >> 1) * 16 + (c4 & 1) * 8 + (lid >> 2);
            const float* p = xch + rl * 6;
            float om = p[0], os = p[1], omv = p[2];
            int oj = __float_as_int(p[3]);
            float od = p[4], ow = p[5];
            float M = fmaxf(rm[c4], om);
            float s2 = rs[c4] * __expf(rm[c4] - M) + os * __expf(om - M);
            float mv2 = rmv[c4]; int mj2 = rmj[c4];
            if (omv > mv2 || (omv == mv2 && oj < mj2)) { mv2 = omv; mj2 = oj; }
            float dot2 = rdot[c4] + od, wr2 = rwr[c4] + ow;

            int row = bx * 128 + rl;
            float4* g = (float4*)(g_part + ((size_t)row * NSPLIT + by) * 8);
            g[0] = make_float4(M, s2, mv2, __int_as_float(mj2));
            g[1] = make_float4(dot2, wr2, 0.0f, 0.0f);
        }
    }
}

// ---------------- merge: one warp per row (lane = split) + finalize -----------
// Grid: 512 blocks x 256 threads (8 warps/block, 1 row/warp).
__global__ void __launch_bounds__(256) k_merge(const int* __restrict__ qid,
                                               float* __restrict__ out, int out_size) {
    __shared__ double lred[8];
    __shared__ int    ared[8];
    __shared__ unsigned done;
    const int tid = threadIdx.x;
    const int lid = tid & 31;
    const int row = blockIdx.x * 8 + (tid >> 5);
    const unsigned fullm = 0xffffffffu;

    const float4* g = (const float4*)(g_part + ((size_t)row * NSPLIT + lid) * 8);
    float4 p0 = g[0], p1 = g[1];
    float m = p0.x, s = p0.y, mv = p0.z;
    int mj = __float_as_int(p0.w);
    float dot = p1.x, wr = p1.y;

    // 32-lane butterfly reduce (all ops associative+commutative)
#pragma unroll
    for (int off = 16; off > 0; off >>= 1) {
        float om  = __shfl_xor_sync(fullm, m, off);
        float os  = __shfl_xor_sync(fullm, s, off);
        float omv = __shfl_xor_sync(fullm, mv, off);
        int   oj  = __shfl_xor_sync(fullm, mj, off);
        float od  = __shfl_xor_sync(fullm, dot, off);
        float ow  = __shfl_xor_sync(fullm, wr, off);
        float M = fmaxf(m, om);
        s = s * __expf(m - M) + os * __expf(om - M);
        m = M;
        if (omv > mv || (omv == mv && oj < mj)) { mv = omv; mj = oj; }
        dot += od;
        wr += ow;
    }

    if (lid == 0) {
        float lse = m + logf(s);
        lred[tid >> 5] = (double)(wr * lse - dot);
        ared[tid >> 5] = (qid[mj] == qid[row]) ? 1 : 0;
    }
    __syncthreads();
    if (tid == 0) {
        double lsum = 0.0; int asum = 0;
#pragma unroll
        for (int i = 0; i < 8; i++) { lsum += lred[i]; asum += ared[i]; }
        atomicAdd(&g_loss, lsum);
        atomicAdd(&g_acc, asum);
        __threadfence();
        done = atomicAdd(&g_ticket, 1u);
    }
    __syncthreads();
    if (done == gridDim.x - 1) {   // last block to finish
        if (tid == 0) {
            if (out_size > 0) out[0] = (float)(g_loss / (double)BATCH);
            if (out_size > 1) out[1] = (float)g_acc / (float)BATCH;
        }
    }
}

// ---------------- launch -------------------------------------------------------
extern "C" void kernel_launch(void* const* d_in, const int* in_sizes, int n_in,
                              void* d_out, int out_size) {
    const float* Q      = (const float*)d_in[0];
    const float* A      = (const float*)d_in[1];
    const int*   qid    = (const int*)d_in[2];
    const float* ranks  = (const float*)d_in[3];
    const float* scores = (const float*)d_in[4];
    float* out = (float*)d_out;

    cudaFuncSetAttribute(k_mma, cudaFuncAttributeMaxDynamicSharedMemorySize, SMEM_TOTAL);

    k_pre<<<4097, 256>>>(scores, ranks, qid, Q, A);
    k_mma<<<dim3(32, 32), 256, SMEM_TOTAL>>>(qid);
    k_merge<<<512, 256>>>(qid, out, out_size);
}

// round 16
// speedup vs baseline: 1.0677x; 1.0677x over previous
#include <cuda_runtime.h>
#include <cuda_fp16.h>
#include <math.h>

#define BATCH 4096
#define DIM 1024
#define NG 1024
#define NSPLIT 32            // column splits (one per by-CTA after wn merge)
#define TEMP_INV 10.0f

// ---------------- scratch ----------------------------------------------------
__device__ __align__(16) unsigned short g_qh[BATCH * DIM];
__device__ __align__(16) unsigned short g_ah[BATCH * DIM];

__device__ float  g_w[BATCH];
__device__ __align__(16) float g_part[BATCH * NSPLIT * 8];  // packed: m,s,mv,mj,dot,wr,pad,pad
__device__ double g_loss;
__device__ int    g_acc;
__device__ unsigned g_ticket;

// ---------------- PTX helpers -------------------------------------------------
__device__ __forceinline__ unsigned smem_u32(const void* p) {
    unsigned a;
    asm("{ .reg .u64 t; cvta.to.shared.u64 t, %1; cvt.u32.u64 %0, t; }" : "=r"(a) : "l"(p));
    return a;
}

__device__ __forceinline__ void cp16(unsigned dst, const void* src) {
    asm volatile("cp.async.cg.shared.global [%0], [%1], 16;" :: "r"(dst), "l"(src) : "memory");
}
__device__ __forceinline__ void cp_commit() {
    asm volatile("cp.async.commit_group;" ::: "memory");
}
template <int N>
__device__ __forceinline__ void cp_wait() {
    asm volatile("cp.async.wait_group %0;" :: "n"(N) : "memory");
}

__device__ __forceinline__ void ldsm4(unsigned& r0, unsigned& r1, unsigned& r2, unsigned& r3,
                                      unsigned addr) {
    asm volatile("ldmatrix.sync.aligned.m8n8.x4.shared.b16 {%0,%1,%2,%3}, [%4];"
        : "=r"(r0), "=r"(r1), "=r"(r2), "=r"(r3) : "r"(addr));
}

__device__ __forceinline__ void mma_f16(float* c, unsigned a0, unsigned a1, unsigned a2,
                                        unsigned a3, unsigned b0, unsigned b1) {
    asm volatile(
        "mma.sync.aligned.m16n8k16.row.col.f32.f16.f16.f32 "
        "{%0,%1,%2,%3}, {%4,%5,%6,%7}, {%8,%9}, {%0,%1,%2,%3};"
        : "+f"(c[0]), "+f"(c[1]), "+f"(c[2]), "+f"(c[3])
        : "r"(a0), "r"(a1), "r"(a2), "r"(a3), "r"(b0), "r"(b1));
}

// ---------------- weight prep (single CTA, 1024 threads; smem group arrays) ---
__global__ void __launch_bounds__(1024) k_prep(const float* __restrict__ scores,
                                               const float* __restrict__ ranks,
                                               const int* __restrict__ qid) {
    __shared__ int   smax[NG];
    __shared__ int   smin[NG];
    __shared__ float wsum[NG];
    const int tid = threadIdx.x;

    if (tid < NG) {
        smax[tid] = 0xFF800000;   // -inf bits (scores >= 0 so int order works)
        smin[tid] = 0x7F800000;
        wsum[tid] = 0.0f;
    }
    if (tid == 0) { g_loss = 0.0; g_acc = 0; g_ticket = 0; }
    __syncthreads();

    int   gi[4];
    float sc[4], wv[4];
#pragma unroll
    for (int i = 0; i < 4; i++) {
        int idx = tid + i * 1024;
        gi[i] = qid[idx];
        sc[i] = scores[idx];
        atomicMax(&smax[gi[i]], __float_as_int(sc[i]));
        atomicMin(&smin[gi[i]], __float_as_int(sc[i]));
    }
    __syncthreads();

#pragma unroll
    for (int i = 0; i < 4; i++) {
        int idx = tid + i * 1024;
        float w = expf(-0.1f * ranks[idx]);
        float mx = __int_as_float(smax[gi[i]]);
        float mn = __int_as_float(smin[gi[i]]);
        float den = mx - mn;
        float norm = (den > 0.0f) ? (sc[i] - mn) / den : 0.0f;
        w *= expf(0.01f * norm);
        wv[i] = w;
        atomicAdd(&wsum[gi[i]], w);
    }
    __syncthreads();

#pragma unroll
    for (int i = 0; i < 4; i++) {
        int idx = tid + i * 1024;
        g_w[idx] = wv[i] / wsum[gi[i]];
    }
}

// ---------------- fp32 -> fp16 (row-major) ------------------------------------
__global__ void k_convert(const float* __restrict__ Q, const float* __restrict__ A) {
    int idx = blockIdx.x * blockDim.x + threadIdx.x;   // 0 .. 524287
    const float* src = (blockIdx.y == 0) ? Q : A;
    unsigned short* dh = (blockIdx.y == 0) ? g_qh : g_ah;

    size_t e0 = (size_t)idx * 8;
    float4 f0 = *(const float4*)(src + e0);
    float4 f1 = *(const float4*)(src + e0 + 4);
    float v[8] = {f0.x, f0.y, f0.z, f0.w, f1.x, f1.y, f1.z, f1.w};

    unsigned short hs[8];
#pragma unroll
    for (int i = 0; i < 8; i++) hs[i] = __half_as_ushort(__float2half_rn(v[i]));
    uint4 hp;
    hp.x = (unsigned)hs[0] | ((unsigned)hs[1] << 16);
    hp.y = (unsigned)hs[2] | ((unsigned)hs[3] << 16);
    hp.z = (unsigned)hs[4] | ((unsigned)hs[5] << 16);
    hp.w = (unsigned)hs[6] | ((unsigned)hs[7] << 16);
    *(uint4*)(dh + e0) = hp;
}

// ---------------- main: fp16 mma.sync GEMM + fused epilogue -------------------
// Grid (32, 32): CTA tile rows [bx*128,+128) x cols [by*128,+128).
// 8 warps as 4(m) x 2(n); warp tile 32 x 64. BK = 64, 16 k-iters,
// 3-stage cp.async pipeline (one sync per iter).
// smem: sq[128] int @0, sw[128] float @512, stages @1024: 3 x (2 tiles x 18432B)
// After mainloop the stage area is reused as the wn0<-wn1 exchange buffer.
#define TILE_B  18432u            // 128 rows x 72 halfs x 2B (144B stride: LDSM conflict-free)
#define STG_OFF 1024u
#define STG_SZ  (2u * TILE_B)     // 36864
#define NSTAGE  3
#define NKIT    16
#define SMEM_TOTAL (1024 + NSTAGE * 36864)

__global__ void __launch_bounds__(256) k_mma(const int* __restrict__ qid) {
    extern __shared__ char smem[];
    const unsigned sb = smem_u32(smem);
    const int tid = threadIdx.x;
    const int wid = tid >> 5;
    const int lid = tid & 31;
    const int wm = wid & 3;        // m warp 0..3
    const int wn = wid >> 2;       // n warp 0..1
    const int bx = blockIdx.x, by = blockIdx.y;

    // column tables
    if (tid < 128) {
        int c = by * 128 + tid;
        ((int*)(smem))[tid] = qid[c];
        ((float*)(smem + 512))[tid] = g_w[c];
    }

    float acc[2][8][4];
#pragma unroll
    for (int i = 0; i < 2; i++)
#pragma unroll
        for (int j = 0; j < 8; j++)
#pragma unroll
            for (int k = 0; k < 4; k++) acc[i][j][k] = 0.0f;

    // ---- async load of one BK=64 chunk (2 tiles x 128 rows x 128B) ----------
    auto load_chunk = [&](int kc) {
        if (kc < NKIT) {
            unsigned stg = sb + STG_OFF + (unsigned)(kc % NSTAGE) * STG_SZ;
#pragma unroll
            for (int c8 = 0; c8 < 8; c8++) {
                int c = tid + c8 * 256;          // 0..2047
                int tile = c >> 10;              // 0: qh, 1: ah
                int ci = c & 1023;
                int row = ci >> 3;
                int j = ci & 7;
                const unsigned short* base = (tile == 0) ? g_qh : g_ah;
                int grow = ((tile == 0) ? bx : by) * 128 + row;
                const unsigned short* src = base + (size_t)grow * DIM + kc * 64 + 8 * j;
                unsigned dst = stg + tile * TILE_B + row * 144 + 16 * j;
                cp16(dst, src);
            }
        }
        cp_commit();   // constant group count, even past the end
    };

    // A-fragment lane address pieces (row-major m16 x k16 via x4)
    const int a_r = (lid & 15);
    const int a_k = (lid >> 4) << 3;
    // B-fragment lane address pieces (two n8 tiles per x4)
    const int b_n = ((lid >> 4) << 3) + (lid & 7);
    const int b_k = ((lid >> 3) & 1) << 3;

    load_chunk(0);
    load_chunk(1);

    for (int kc = 0; kc < NKIT; kc++) {
        cp_wait<1>();         // chunk kc's own stores complete (kc+1 may pend)
        __syncthreads();      // visibility of chunk kc; frees buf (kc+2)%3
        load_chunk(kc + 2);   // prefetch 2 ahead (empty commit past end)

        unsigned stg = sb + STG_OFF + (unsigned)(kc % NSTAGE) * STG_SZ;
        unsigned qhb = stg;
        unsigned ahb = stg + TILE_B;

#pragma unroll
        for (int ks = 0; ks < 4; ks++) {
            const int ko = ks * 16;
            unsigned a[2][4], b[4][4];
#pragma unroll
            for (int mt = 0; mt < 2; mt++) {
                unsigned ad = qhb + (wm * 32 + mt * 16 + a_r) * 144 + (ko + a_k) * 2;
                ldsm4(a[mt][0], a[mt][1], a[mt][2], a[mt][3], ad);
            }
#pragma unroll
            for (int p = 0; p < 4; p++) {
                unsigned ad = ahb + (wn * 64 + p * 16 + b_n) * 144 + (ko + b_k) * 2;
                ldsm4(b[p][0], b[p][1], b[p][2], b[p][3], ad);
            }
#pragma unroll
            for (int mt = 0; mt < 2; mt++)
#pragma unroll
                for (int p = 0; p < 4; p++) {
                    mma_f16(acc[mt][2 * p],     a[mt][0], a[mt][1], a[mt][2], a[mt][3], b[p][0], b[p][1]);
                    mma_f16(acc[mt][2 * p + 1], a[mt][0], a[mt][1], a[mt][2], a[mt][3], b[p][2], b[p][3]);
                }
        }
    }

    // ---- fused epilogue -----------------------------------------------------
    const int* sq = (const int*)(smem);
    const float* swt = (const float*)(smem + 512);
    const unsigned fullm = 0xffffffffu;

    float rm[4], rs[4], rmv[4], rdot[4], rwr[4];
    int rmj[4];

#pragma unroll
    for (int c4 = 0; c4 < 4; c4++) {
        const int mt = c4 >> 1, h = c4 & 1;
        int row = bx * 128 + wm * 32 + mt * 16 + h * 8 + (lid >> 2);
        int rq = qid[row];
        float m = -1e30f, s = 0.0f, mv = -1e30f, dot = 0.0f, wr = 0.0f;
        int mj = 0;
#pragma unroll
        for (int nt = 0; nt < 8; nt++) {
#pragma unroll
            for (int b = 0; b < 2; b++) {
                float val = acc[mt][nt][2 * h + b] * TEMP_INV;
                int cl = wn * 64 + nt * 8 + 2 * (lid & 3) + b;
                if (val > m) {
                    s = s * __expf(m - val) + 1.0f;
                    m = val;
                } else {
                    s += __expf(val - m);
                }
                if (val > mv) { mv = val; mj = by * 128 + cl; }
                if (sq[cl] == rq) {
                    float wj = swt[cl];
                    dot = fmaf(wj, val, dot);
                    wr += wj;
                }
            }
        }
        // reduce across the 4 lanes owning this row (lanes 4k..4k+3)
#pragma unroll
        for (int off = 2; off > 0; off >>= 1) {
            float om  = __shfl_down_sync(fullm, m, off, 4);
            float os  = __shfl_down_sync(fullm, s, off, 4);
            float omv = __shfl_down_sync(fullm, mv, off, 4);
            int   oj  = __shfl_down_sync(fullm, mj, off, 4);
            float od  = __shfl_down_sync(fullm, dot, off, 4);
            float ow  = __shfl_down_sync(fullm, wr, off, 4);
            float M = fmaxf(m, om);
            s = s * __expf(m - M) + os * __expf(om - M);
            m = M;
            if (omv > mv || (omv == mv && oj < mj)) { mv = omv; mj = oj; }
            dot += od;
            wr += ow;
        }
        rm[c4] = m; rs[c4] = s; rmv[c4] = mv; rmj[c4] = mj; rdot[c4] = dot; rwr[c4] = wr;
    }

    // ---- wn1 -> wn0 exchange through smem, then one packed store per row ----
    cp_wait<0>();          // drain trailing empty groups before reusing stage smem
    __syncthreads();
    float* xch = (float*)(smem + STG_OFF);   // 128 rows x 6 floats

    if (wn == 1 && (lid & 3) == 0) {
#pragma unroll
        for (int c4 = 0; c4 < 4; c4++) {
            int rl = wm * 32 + (c4 >> 1) * 16 + (c4 & 1) * 8 + (lid >> 2);
            float* p = xch + rl * 6;
            p[0] = rm[c4]; p[1] = rs[c4]; p[2] = rmv[c4];
            p[3] = __int_as_float(rmj[c4]); p[4] = rdot[c4]; p[5] = rwr[c4];
        }
    }
    __syncthreads();
    if (wn == 0 && (lid & 3) == 0) {
#pragma unroll
        for (int c4 = 0; c4 < 4; c4++) {
            int rl = wm * 32 + (c4 >> 1) * 16 + (c4 & 1) * 8 + (lid >> 2);
            const float* p = xch + rl * 6;
            float om = p[0], os = p[1], omv = p[2];
            int oj = __float_as_int(p[3]);
            float od = p[4], ow = p[5];
            float M = fmaxf(rm[c4], om);
            float s2 = rs[c4] * __expf(rm[c4] - M) + os * __expf(om - M);
            float mv2 = rmv[c4]; int mj2 = rmj[c4];
            if (omv > mv2 || (omv == mv2 && oj < mj2)) { mv2 = omv; mj2 = oj; }
            float dot2 = rdot[c4] + od, wr2 = rwr[c4] + ow;

            int row = bx * 128 + rl;
            float4* g = (float4*)(g_part + ((size_t)row * NSPLIT + by) * 8);
            g[0] = make_float4(M, s2, mv2, __int_as_float(mj2));
            g[1] = make_float4(dot2, wr2, 0.0f, 0.0f);
        }
    }
}

// ---------------- merge: one warp per row (lane = split) + finalize -----------
// Grid: 512 blocks x 256 threads (8 warps/block, 1 row/warp).
__global__ void __launch_bounds__(256) k_merge(const int* __restrict__ qid,
                                               float* __restrict__ out, int out_size) {
    __shared__ double lred[8];
    __shared__ int    ared[8];
    __shared__ unsigned done;
    const int tid = threadIdx.x;
    const int lid = tid & 31;
    const int row = blockIdx.x * 8 + (tid >> 5);
    const unsigned fullm = 0xffffffffu;

    const float4* g = (const float4*)(g_part + ((size_t)row * NSPLIT + lid) * 8);
    float4 p0 = g[0], p1 = g[1];
    float m = p0.x, s = p0.y, mv = p0.z;
    int mj = __float_as_int(p0.w);
    float dot = p1.x, wr = p1.y;

    // 32-lane butterfly reduce (all ops associative+commutative)
#pragma unroll
    for (int off = 16; off > 0; off >>= 1) {
        float om  = __shfl_xor_sync(fullm, m, off);
        float os  = __shfl_xor_sync(fullm, s, off);
        float omv = __shfl_xor_sync(fullm, mv, off);
        int   oj  = __shfl_xor_sync(fullm, mj, off);
        float od  = __shfl_xor_sync(fullm, dot, off);
        float ow  = __shfl_xor_sync(fullm, wr, off);
        float M = fmaxf(m, om);
        s = s * __expf(m - M) + os * __expf(om - M);
        m = M;
        if (omv > mv || (omv == mv && oj < mj)) { mv = omv; mj = oj; }
        dot += od;
        wr += ow;
    }

    if (lid == 0) {
        float lse = m + logf(s);
        lred[tid >> 5] = (double)(wr * lse - dot);
        ared[tid >> 5] = (qid[mj] == qid[row]) ? 1 : 0;
    }
    __syncthreads();
    if (tid == 0) {
        double lsum = 0.0; int asum = 0;
#pragma unroll
        for (int i = 0; i < 8; i++) { lsum += lred[i]; asum += ared[i]; }
        atomicAdd(&g_loss, lsum);
        atomicAdd(&g_acc, asum);
        __threadfence();
        done = atomicAdd(&g_ticket, 1u);
    }
    __syncthreads();
    if (done == gridDim.x - 1) {   // last block to finish
        if (tid == 0) {
            if (out_size > 0) out[0] = (float)(g_loss / (double)BATCH);
            if (out_size > 1) out[1] = (float)g_acc / (float)BATCH;
        }
    }
}

// ---------------- launch -------------------------------------------------------
extern "C" void kernel_launch(void* const* d_in, const int* in_sizes, int n_in,
                              void* d_out, int out_size) {
    const float* Q      = (const float*)d_in[0];
    const float* A      = (const float*)d_in[1];
    const int*   qid    = (const int*)d_in[2];
    const float* ranks  = (const float*)d_in[3];
    const float* scores = (const float*)d_in[4];
    float* out = (float*)d_out;

    cudaFuncSetAttribute(k_mma, cudaFuncAttributeMaxDynamicSharedMemorySize, SMEM_TOTAL);

    k_prep<<<1, 1024>>>(scores, ranks, qid);
    k_convert<<<dim3(2048, 2), 256>>>(Q, A);
    k_mma<<<dim3(32, 32), 256, SMEM_TOTAL>>>(qid);
    k_merge<<<512, 256>>>(qid, out, out_size);
}